// round 15
// baseline (speedup 1.0000x reference)
#include <cuda_runtime.h>
#include <math.h>

#define N 320
#define D 128
#define NMAT 3
#define RHO_C 10.0f
#define MARGIN_C 0.2f
#define TAU_C 1.3f
#define SEMIHARD_THRESH_C 0.01f
#define EPS_C 1e-12f
#define NTRI  210                // 20*21/2 lower-triangle 16x16 tiles
#define NCH   4                  // k chunks
#define KCH   80                 // k-chunk size (N/4)
#define GRID  640                // co-resident: 5 blocks/SM x 148 SMs = 740 >= 640
#define PADW 132

typedef unsigned long long ull;

// ---------------- device scratch (no allocations allowed) ----------------
__device__ float  g_d[NMAT][N][N];   // pairwise distances per matrix
__device__ float2 g_t2[N][N];        // (-d_emb[i][k], bk = 1-pw[i][k])
__device__ float  g_pw[N][N];        // pair weights
__device__ float2 g_mm[NCH][N][N];   // per-chunk (maxs, minn) partials
__device__ float  g_partden[GRID];   // phase-B block partial sums of pw
__device__ float  g_pnum[N];         // per-i sums of pos*pair_w
__device__ unsigned int g_cnt_i[N];  // per-i chunk tickets
__device__ unsigned int g_counter;   // global ticket for final
__device__ unsigned int g_bars[2];   // phase barriers (reset by final winner)

// ---------------- packed f32x2 helpers (per-lane bit-identical to scalar) ---
__device__ __forceinline__ ull add2(ull a, ull b) {
    ull r; asm("add.rn.f32x2 %0, %1, %2;" : "=l"(r) : "l"(a), "l"(b)); return r;
}
__device__ __forceinline__ ull mul2(ull a, ull b) {
    ull r; asm("mul.rn.f32x2 %0, %1, %2;" : "=l"(r) : "l"(a), "l"(b)); return r;
}
__device__ __forceinline__ ull fma2(ull a, ull b, ull c) {
    ull r; asm("fma.rn.f32x2 %0, %1, %2, %3;" : "=l"(r) : "l"(a), "l"(b), "l"(c)); return r;
}
__device__ __forceinline__ ull pack2(float lo, float hi) {
    ull r; asm("mov.b64 %0, {%1, %2};" : "=l"(r) : "f"(lo), "f"(hi)); return r;
}
__device__ __forceinline__ void unpack2(ull p, float& lo, float& hi) {
    asm("mov.b64 {%0, %1}, %2;" : "=f"(lo), "=f"(hi) : "l"(p));
}

// grid-wide barrier: safe because the full grid is co-resident (wave 1).
__device__ __forceinline__ void gbar(int idx) {
    __syncthreads();
    if (threadIdx.x == 0) {
        __threadfence();
        unsigned a = atomicAdd(&g_bars[idx], 1u);
        if (a + 1u < (unsigned)GRID) {
            volatile unsigned* p = &g_bars[idx];
            while (*p < (unsigned)GRID) __nanosleep(64);
        }
    }
    __syncthreads();
}

struct SDist {
    float Ai[16][PADW];
    float Aj[16][PADW];
    float sq[32];
    float ri[32];
};

__global__ void __launch_bounds__(320, 5) k_all(const float* __restrict__ src,
                                                const float* __restrict__ emb,
                                                float* __restrict__ out) {
    int b = blockIdx.x;
    int t = threadIdx.x;
    int lane = t & 31, warp = t >> 5;

    __shared__ SDist sd;
    __shared__ __align__(16) float sndk[KCH];
    __shared__ __align__(16) float sbk[KCH];
    __shared__ float sred[10], sred2[10];
    __shared__ bool sflag;

    // ================= phase A: distance tiles (1 per block) =================
    if (b < NMAT * NTRI) {
        int m  = b / NTRI;
        int bt = b - m * NTRI;
        int bi = (int)((sqrtf(8.0f * (float)bt + 1.0f) - 1.0f) * 0.5f);
        while ((bi + 1) * (bi + 2) / 2 <= bt) bi++;
        while (bi * (bi + 1) / 2 > bt) bi--;
        int bj = bt - bi * (bi + 1) / 2;
        int i0 = bi * 16, j0 = bj * 16;
        int tx = t & 15, ty = t >> 4;     // ty = 0..19 (320 threads)

        const float* base = (m < 2) ? (src + (size_t)m * N * D) : emb;
        for (int e = t; e < 16 * 32; e += 320) {
            int r = e >> 5, c4 = e & 31;
            *(float4*)&sd.Ai[r][c4 * 4] = ((const float4*)(base + (size_t)(i0 + r) * D))[c4];
            *(float4*)&sd.Aj[r][c4 * 4] = ((const float4*)(base + (size_t)(j0 + r) * D))[c4];
        }
        __syncthreads();

        // warp-cooperative row norms: 10 warps, 32 rows -> warps 0..7 do 4 rows,
        // warps 8,9 idle (keeps per-row float4/shuffle order bitwise identical)
        if (warp < 8) {
            #pragma unroll
            for (int rr = 0; rr < 4; rr++) {
                int row = warp * 4 + rr;
                const float* rp = (row < 16) ? &sd.Ai[row][0] : &sd.Aj[row - 16][0];
                float4 x = ((const float4*)rp)[lane];
                float ssum = x.x * x.x + x.y * x.y + x.z * x.z + x.w * x.w;
                #pragma unroll
                for (int o = 16; o > 0; o >>= 1) ssum += __shfl_xor_sync(0xffffffffu, ssum, o);
                if (lane == 0) {
                    float rn = 1.0f / fmaxf(sqrtf(ssum), EPS_C);
                    sd.sq[row] = ssum * (rn * rn);
                    sd.ri[row] = rn;
                }
            }
        }
        __syncthreads();

        // 320 threads over 256 outputs: ty<16 computes; keeps warp shape simple
        if (ty < 16) {
            const float4* ai = (const float4*)&sd.Ai[ty][0];
            const float4* aj = (const float4*)&sd.Aj[tx][0];
            float d0 = 0.f, d1 = 0.f, d2a = 0.f, d3 = 0.f;
            #pragma unroll 8
            for (int c = 0; c < 32; c++) {
                float4 a  = ai[c];
                float4 bb = aj[c];
                d0  += a.x * bb.x;
                d1  += a.y * bb.y;
                d2a += a.z * bb.z;
                d3  += a.w * bb.w;
            }
            float dot = (d0 + d1) + (d2a + d3);
            float rij = sd.ri[ty] * sd.ri[16 + tx];
            float dd  = sd.sq[ty] + sd.sq[16 + tx] - 2.0f * (dot * rij);
            float d   = sqrtf(fmaxf(dd, 0.0f) + EPS_C);
            int i = i0 + ty, j = j0 + tx;
            g_d[m][i][j] = d;
            if (bi != bj) g_d[m][j][i] = d;   // bitwise symmetric by construction
        }
    }
    gbar(0);

    // ================= phase B: pw table + den partials ======================
    {
        int idx = b * 320 + t;
        float pw = 0.0f;
        if (idx < N * N) {
            float a0 = __ldcg(&(&g_d[0][0][0])[idx]);
            float a1 = __ldcg(&(&g_d[1][0][0])[idx]);
            float de = __ldcg(&(&g_d[2][0][0])[idx]);
            pw = 1.0f / (1.0f + expf(-RHO_C * (TAU_C - 0.5f * (a0 + a1))));
            __stcg(&(&g_t2[0][0])[idx], make_float2(-de, 1.0f - pw));
            __stcg(&(&g_pw[0][0])[idx], pw);
        }
        float v = pw;
        #pragma unroll
        for (int o = 16; o > 0; o >>= 1) v += __shfl_down_sync(0xffffffffu, v, o);
        if (lane == 0) sred[warp] = v;
        __syncthreads();
        if (t == 0) {
            float w = 0.0f;
            #pragma unroll
            for (int q = 0; q < 10; q++) w += sred[q];
            g_partden[b] = w;
        }
    }
    gbar(1);

    // ================= phase C: triplet tasks (2 per block) ==================
    for (int task = b; task < NCH * N; task += GRID) {
        int i  = task >> 2;
        int kc = task & 3;

        __syncthreads();   // protect smem reuse across tasks/phases
        float2 own = __ldcg(&g_t2[i][t]);       // (-dij, bkj)
        float pwij = __ldcg(&g_pw[i][t]);
        if (t < KCH) {
            float2 c = __ldcg(&g_t2[i][kc * KCH + t]);
            sndk[t] = c.x;
            sbk[t]  = c.y;
        }
        __syncthreads();

        float dij = -own.x;
        ull dij2  = pack2(dij, dij);
        ull M2    = pack2(MARGIN_C, MARGIN_C);
        float nrpw = -(RHO_C * pwij);
        ull nrpw2 = pack2(nrpw, nrpw);

        float mx0 = 0.0f, mx1 = 0.0f, mx2 = 0.0f, mx3 = 0.0f;
        float mn0 = 1e30f, mn1 = 1e30f, mn2 = 1e30f, mn3 = 1e30f;

        const ulonglong2* pnd = (const ulonglong2*)sndk;
        const ulonglong2* pbk = (const ulonglong2*)sbk;

        // Per lane: tt = dij + (-dk) == -(dk - dij) bitwise; m = M + tt == M - diff.
        // k==j -> tt==0 exactly -> m==0.2f exactly -> semihard (m <= MARGIN).
        #pragma unroll 5
        for (int q = 0; q < KCH / 4; q++) {
            ulonglong2 nd = pnd[q];
            ulonglong2 bb = pbk[q];
            {
                ull t2  = add2(dij2, nd.x);
                ull m2  = add2(M2, t2);
                ull vs2 = mul2(m2, bb.x);
                ull vh2 = fma2(bb.x, nrpw2, m2);
                float m0, m1, vs0, vs1, vh0, vh1;
                unpack2(m2, m0, m1); unpack2(vs2, vs0, vs1); unpack2(vh2, vh0, vh1);
                if (m0 <= MARGIN_C) mx0 = fmaxf(mx0, vs0); else mn0 = fminf(mn0, vh0);
                if (m1 <= MARGIN_C) mx1 = fmaxf(mx1, vs1); else mn1 = fminf(mn1, vh1);
            }
            {
                ull t2  = add2(dij2, nd.y);
                ull m2  = add2(M2, t2);
                ull vs2 = mul2(m2, bb.y);
                ull vh2 = fma2(bb.y, nrpw2, m2);
                float m0, m1, vs0, vs1, vh0, vh1;
                unpack2(m2, m0, m1); unpack2(vs2, vs0, vs1); unpack2(vh2, vh0, vh1);
                if (m0 <= MARGIN_C) mx2 = fmaxf(mx2, vs0); else mn2 = fminf(mn2, vh0);
                if (m1 <= MARGIN_C) mx3 = fmaxf(mx3, vs1); else mn3 = fminf(mn3, vh1);
            }
        }
        float maxs = fmaxf(fmaxf(mx0, mx1), fmaxf(mx2, mx3));  // assoc+comm: bit-exact
        float minn = fminf(fminf(mn0, mn1), fminf(mn2, mn3));

        __stcg(&g_mm[kc][i][t], make_float2(maxs, minn));
        __threadfence();

        if (t == 0) sflag = (atomicAdd(&g_cnt_i[i], 1u) == (unsigned)(NCH - 1));
        __syncthreads();
        if (!sflag) continue;

        // ---- winner: combine row i ----
        float2 c0 = __ldcg(&g_mm[0][i][t]);
        float2 c1 = __ldcg(&g_mm[1][i][t]);
        float2 c2 = __ldcg(&g_mm[2][i][t]);
        float2 c3 = __ldcg(&g_mm[3][i][t]);
        float mx = fmaxf(fmaxf(c0.x, c1.x), fmaxf(c2.x, c3.x));
        float mn = fminf(fminf(c0.y, c1.y), fminf(c2.y, c3.y));
        float psh = pwij * mx;                          // pos_semihard
        float ph  = (mn < 0.0f) ? (mn + RHO_C) : 0.0f;
        float pos = psh + ((psh <= SEMIHARD_THRESH_C) ? ph : 0.0f);
        float contrib = pos * pwij;

        float v = contrib;
        #pragma unroll
        for (int o = 16; o > 0; o >>= 1) v += __shfl_down_sync(0xffffffffu, v, o);
        if (lane == 0) sred[warp] = v;
        __syncthreads();
        if (t == 0) {
            float sn = 0.0f;
            #pragma unroll
            for (int q = 0; q < 10; q++) sn += sred[q];
            __stcg(&g_pnum[i], sn);
        }

        // ---- final: last row-winner sums everything, then resets state ----
        __threadfence();
        if (t == 0) sflag = (atomicAdd(&g_counter, 1u) == (unsigned)(N - 1));
        __syncthreads();
        if (!sflag) continue;

        float num = __ldcg(&g_pnum[t]);
        float den = __ldcg(&g_partden[t]) + __ldcg(&g_partden[t + 320]);
        #pragma unroll
        for (int o = 16; o > 0; o >>= 1) {
            num += __shfl_down_sync(0xffffffffu, num, o);
            den += __shfl_down_sync(0xffffffffu, den, o);
        }
        if (lane == 0) { sred[warp] = num; sred2[warp] = den; }
        __syncthreads();
        if (t == 0) {
            float fn = 0.0f, fd = 0.0f;
            #pragma unroll
            for (int q = 0; q < 10; q++) { fn += sred[q]; fd += sred2[q]; }
            out[0] = (fd > 0.0f) ? (fn / fmaxf(fd, EPS_C)) : 0.0f;
        }
        // reset tickets/barriers for the next launch (safe: every counter's
        // last reader is ordered before this point by the ticket chain)
        g_cnt_i[t] = 0;
        if (t == 0) g_counter = 0;
        if (t < 2)  g_bars[t] = 0;
    }
}

extern "C" void kernel_launch(void* const* d_in, const int* in_sizes, int n_in,
                              void* d_out, int out_size) {
    (void)n_in; (void)out_size;
    const float* src = (const float*)d_in[0];
    const float* emb = (const float*)d_in[1];
    if (n_in >= 2 && in_sizes[0] == N * D && in_sizes[1] == 2 * N * D) {
        const float* tmp = src; src = emb; emb = tmp;
    }
    float* out = (float*)d_out;

    k_all<<<GRID, 320>>>(src, emb, out);
}

// round 16
// speedup vs baseline: 1.1922x; 1.1922x over previous
#include <cuda_runtime.h>
#include <math.h>

#define N 320
#define D 128
#define NMAT 3
#define RHO_C 10.0f
#define MARGIN_C 0.2f
#define TAU_C 1.3f
#define SEMIHARD_THRESH_C 0.01f
#define EPS_C 1e-12f
#define NTRI32 55                // 10*11/2 lower-triangle 32x32 tiles
#define NCH   4                  // k chunks
#define KCH   80                 // k-chunk size (N/4)
#define PADW 132

typedef unsigned long long ull;

// ---------------- device scratch (no allocations allowed) ----------------
__device__ float  g_d[NMAT][N][N];   // pairwise distances per matrix
__device__ float2 g_t2[N][N];        // (-d_emb[i][k], bk = 1-pw[i][k])
__device__ float  g_pw[N][N];        // pair weights
__device__ float2 g_mm[NCH][N][N];   // per-chunk (maxs, minn) partials
__device__ float  g_partden[400];    // k_prep block partial sums of pw
__device__ float  g_pnum[N];         // per-i sums of pos*pair_w
__device__ unsigned int g_cnt_i[N];  // per-i chunk tickets
__device__ unsigned int g_counter;   // global ticket for fused final

// ---------------- packed f32x2 helpers (per-lane bit-identical to scalar) ---
__device__ __forceinline__ ull add2(ull a, ull b) {
    ull r; asm("add.rn.f32x2 %0, %1, %2;" : "=l"(r) : "l"(a), "l"(b)); return r;
}
__device__ __forceinline__ ull mul2(ull a, ull b) {
    ull r; asm("mul.rn.f32x2 %0, %1, %2;" : "=l"(r) : "l"(a), "l"(b)); return r;
}
__device__ __forceinline__ ull fma2(ull a, ull b, ull c) {
    ull r; asm("fma.rn.f32x2 %0, %1, %2, %3;" : "=l"(r) : "l"(a), "l"(b), "l"(c)); return r;
}
__device__ __forceinline__ ull pack2(float lo, float hi) {
    ull r; asm("mov.b64 %0, {%1, %2};" : "=l"(r) : "f"(lo), "f"(hi)); return r;
}
__device__ __forceinline__ void unpack2(ull p, float& lo, float& hi) {
    asm("mov.b64 {%0, %1}, %2;" : "=f"(lo), "=f"(hi) : "l"(p));
}

// ---------------- kernel 1: distances; 165 blocks = 55 32x32 tiles x 3 mats -
// 2x2 register blocking: 1 LDS.128 per output per c-iter (halves the smem
// crossbar traffic that bound the 16x16 version at 11.2us / issue=37%).
__global__ void __launch_bounds__(256) k_dist(const float* __restrict__ src,
                                              const float* __restrict__ emb) {
    int b  = blockIdx.x;
    int m  = b / NTRI32;
    int bt = b - m * NTRI32;
    int bi = (int)((sqrtf(8.0f * (float)bt + 1.0f) - 1.0f) * 0.5f);
    while ((bi + 1) * (bi + 2) / 2 <= bt) bi++;
    while (bi * (bi + 1) / 2 > bt) bi--;
    int bj = bt - bi * (bi + 1) / 2;
    int i0 = bi * 32, j0 = bj * 32;

    __shared__ float Ai[32][PADW];
    __shared__ float Aj[32][PADW];
    __shared__ float s_sq[64];   // [0..31]=i rows, [32..63]=j rows
    __shared__ float s_ri[64];

    int t  = threadIdx.x;
    int tx = t & 15, ty = t >> 4;      // 16x16 thread tile, each does 2x2
    int lane = t & 31, warp = t >> 5;

    if (b == 0) {                       // reset tickets (precedes k_tripart)
        if (t == 0) g_counter = 0;
        for (int e = t; e < N; e += 256) g_cnt_i[e] = 0;
    }

    const float* base = (m < 2) ? (src + (size_t)m * N * D) : emb;
    for (int e = t; e < 32 * 32; e += 256) {   // 1024 float4 per side
        int r = e >> 5, c4 = e & 31;
        *(float4*)&Ai[r][c4 * 4] = ((const float4*)(base + (size_t)(i0 + r) * D))[c4];
        *(float4*)&Aj[r][c4 * 4] = ((const float4*)(base + (size_t)(j0 + r) * D))[c4];
    }
    __syncthreads();

    // warp-cooperative row norms: 8 warps x 8 rows = 64 rows
    #pragma unroll
    for (int rr = 0; rr < 8; rr++) {
        int row = warp * 8 + rr;
        const float* rp = (row < 32) ? &Ai[row][0] : &Aj[row - 32][0];
        float4 x = ((const float4*)rp)[lane];
        float ssum = x.x * x.x + x.y * x.y + x.z * x.z + x.w * x.w;
        #pragma unroll
        for (int o = 16; o > 0; o >>= 1) ssum += __shfl_xor_sync(0xffffffffu, ssum, o);
        if (lane == 0) {
            float rn = 1.0f / fmaxf(sqrtf(ssum), EPS_C);
            s_sq[row] = ssum * (rn * rn);
            s_ri[row] = rn;
        }
    }
    __syncthreads();

    // 2x2 outputs: rows {ty, ty+16} x cols {tx, tx+16}
    float acc[4][4];   // [out][component]
    #pragma unroll
    for (int o = 0; o < 4; o++)
        #pragma unroll
        for (int c = 0; c < 4; c++) acc[o][c] = 0.0f;

    const float4* ai0 = (const float4*)&Ai[ty][0];
    const float4* ai1 = (const float4*)&Ai[ty + 16][0];
    const float4* aj0 = (const float4*)&Aj[tx][0];
    const float4* aj1 = (const float4*)&Aj[tx + 16][0];
    #pragma unroll 4
    for (int c = 0; c < 32; c++) {
        float4 a0 = ai0[c], a1 = ai1[c];
        float4 b0 = aj0[c], b1 = aj1[c];
        acc[0][0] += a0.x * b0.x; acc[0][1] += a0.y * b0.y;
        acc[0][2] += a0.z * b0.z; acc[0][3] += a0.w * b0.w;
        acc[1][0] += a0.x * b1.x; acc[1][1] += a0.y * b1.y;
        acc[1][2] += a0.z * b1.z; acc[1][3] += a0.w * b1.w;
        acc[2][0] += a1.x * b0.x; acc[2][1] += a1.y * b0.y;
        acc[2][2] += a1.z * b0.z; acc[2][3] += a1.w * b0.w;
        acc[3][0] += a1.x * b1.x; acc[3][1] += a1.y * b1.y;
        acc[3][2] += a1.z * b1.z; acc[3][3] += a1.w * b1.w;
    }

    #pragma unroll
    for (int o = 0; o < 4; o++) {
        int iy = (o >> 1) ? ty + 16 : ty;
        int jx = (o & 1)  ? tx + 16 : tx;
        float dot = (acc[o][0] + acc[o][1]) + (acc[o][2] + acc[o][3]);
        float rij = s_ri[iy] * s_ri[32 + jx];
        float dd  = s_sq[iy] + s_sq[32 + jx] - 2.0f * (dot * rij);
        float d   = sqrtf(fmaxf(dd, 0.0f) + EPS_C);
        int i = i0 + iy, j = j0 + jx;
        g_d[m][i][j] = d;
        if (bi != bj) g_d[m][j][i] = d;   // bitwise symmetric by construction
    }
}

// ---------------- kernel 2: pair weights table + den partials ---------------
__global__ void __launch_bounds__(256) k_prep() {
    int idx = blockIdx.x * 256 + threadIdx.x;
    float pw = 0.0f;
    if (idx < N * N) {
        float a0 = (&g_d[0][0][0])[idx];
        float a1 = (&g_d[1][0][0])[idx];
        float de = (&g_d[2][0][0])[idx];
        pw = 1.0f / (1.0f + expf(-RHO_C * (TAU_C - 0.5f * (a0 + a1))));
        (&g_t2[0][0])[idx] = make_float2(-de, 1.0f - pw);
        (&g_pw[0][0])[idx] = pw;
    }
    float v = pw;
    #pragma unroll
    for (int o = 16; o > 0; o >>= 1) v += __shfl_down_sync(0xffffffffu, v, o);
    __shared__ float swp[8];
    int lane = threadIdx.x & 31, warp = threadIdx.x >> 5;
    if (lane == 0) swp[warp] = v;
    __syncthreads();
    if (warp == 0) {
        float w = (lane < 8) ? swp[lane] : 0.0f;
        #pragma unroll
        for (int o = 4; o > 0; o >>= 1) w += __shfl_down_sync(0xffffffffu, w, o);
        if (lane == 0) g_partden[blockIdx.x] = w;
    }
}

// ---------------- kernel 3: 4-way split-k triplet (f32x2) + final -----------
// grid: 1280 blocks (i = bx>>2, kc = bx&3), 320 threads (one per j).
__global__ void __launch_bounds__(N) k_tripart(float* __restrict__ out) {
    int i  = blockIdx.x >> 2;
    int kc = blockIdx.x & 3;
    int t  = threadIdx.x;          // j

    __shared__ __align__(16) float sndk[KCH];   // -d_emb[i][k]
    __shared__ __align__(16) float sbk[KCH];    // 1 - pw[i][k]

    float2 own = g_t2[i][t];       // (-dij, bkj)
    float pwij = g_pw[i][t];
    if (t < KCH) {
        float2 c = g_t2[i][kc * KCH + t];
        sndk[t] = c.x;
        sbk[t]  = c.y;
    }
    __syncthreads();

    float dij = -own.x;
    ull dij2  = pack2(dij, dij);
    ull M2    = pack2(MARGIN_C, MARGIN_C);
    float nrpw = -(RHO_C * pwij);
    ull nrpw2 = pack2(nrpw, nrpw);

    float mx0 = 0.0f, mx1 = 0.0f, mx2 = 0.0f, mx3 = 0.0f;
    float mn0 = 1e30f, mn1 = 1e30f, mn2 = 1e30f, mn3 = 1e30f;

    const ulonglong2* pnd = (const ulonglong2*)sndk;
    const ulonglong2* pbk = (const ulonglong2*)sbk;

    // Per lane: tt = dij + (-dk) == -(dk - dij) bitwise; m = M + tt == M - diff.
    // k==j -> tt==0 exactly -> m==0.2f exactly -> semihard (m <= MARGIN).
    #pragma unroll 5
    for (int q = 0; q < KCH / 4; q++) {
        ulonglong2 nd = pnd[q];
        ulonglong2 bb = pbk[q];
        {
            ull t2  = add2(dij2, nd.x);
            ull m2  = add2(M2, t2);
            ull vs2 = mul2(m2, bb.x);
            ull vh2 = fma2(bb.x, nrpw2, m2);
            float m0, m1, vs0, vs1, vh0, vh1;
            unpack2(m2, m0, m1); unpack2(vs2, vs0, vs1); unpack2(vh2, vh0, vh1);
            if (m0 <= MARGIN_C) mx0 = fmaxf(mx0, vs0); else mn0 = fminf(mn0, vh0);
            if (m1 <= MARGIN_C) mx1 = fmaxf(mx1, vs1); else mn1 = fminf(mn1, vh1);
        }
        {
            ull t2  = add2(dij2, nd.y);
            ull m2  = add2(M2, t2);
            ull vs2 = mul2(m2, bb.y);
            ull vh2 = fma2(bb.y, nrpw2, m2);
            float m0, m1, vs0, vs1, vh0, vh1;
            unpack2(m2, m0, m1); unpack2(vs2, vs0, vs1); unpack2(vh2, vh0, vh1);
            if (m0 <= MARGIN_C) mx2 = fmaxf(mx2, vs0); else mn2 = fminf(mn2, vh0);
            if (m1 <= MARGIN_C) mx3 = fmaxf(mx3, vs1); else mn3 = fminf(mn3, vh1);
        }
    }
    float maxs = fmaxf(fmaxf(mx0, mx1), fmaxf(mx2, mx3));  // assoc+comm: bit-exact
    float minn = fminf(fminf(mn0, mn1), fminf(mn2, mn3));

    __stcg(&g_mm[kc][i][t], make_float2(maxs, minn));
    __threadfence();

    __shared__ bool win_i;
    if (t == 0) win_i = (atomicAdd(&g_cnt_i[i], 1u) == (unsigned)(NCH - 1));
    __syncthreads();
    if (!win_i) return;

    float2 c0 = __ldcg(&g_mm[0][i][t]);
    float2 c1 = __ldcg(&g_mm[1][i][t]);
    float2 c2 = __ldcg(&g_mm[2][i][t]);
    float2 c3 = __ldcg(&g_mm[3][i][t]);
    float mx = fmaxf(fmaxf(c0.x, c1.x), fmaxf(c2.x, c3.x));
    float mn = fminf(fminf(c0.y, c1.y), fminf(c2.y, c3.y));
    float psh = pwij * mx;                          // pos_semihard
    float ph  = (mn < 0.0f) ? (mn + RHO_C) : 0.0f;
    float pos = psh + ((psh <= SEMIHARD_THRESH_C) ? ph : 0.0f);
    float contrib = pos * pwij;

    float v = contrib;
    #pragma unroll
    for (int o = 16; o > 0; o >>= 1) v += __shfl_down_sync(0xffffffffu, v, o);
    __shared__ float swn[10];
    int lane = t & 31, warp = t >> 5;
    if (lane == 0) swn[warp] = v;
    __syncthreads();
    if (warp == 0 && lane == 0) {
        float sn = 0.0f;
        #pragma unroll
        for (int q = 0; q < 10; q++) sn += swn[q];
        g_pnum[i] = sn;
    }

    // ---- fused final: last winning block sums everything ----
    __threadfence();
    __shared__ bool is_last;
    if (t == 0) is_last = (atomicAdd(&g_counter, 1u) == (unsigned)(N - 1));
    __syncthreads();
    if (!is_last) return;

    float num = __ldcg(&g_pnum[t]);
    float den = 0.0f;
    for (int b2 = t; b2 < 400; b2 += N) den += __ldcg(&g_partden[b2]);
    #pragma unroll
    for (int o = 16; o > 0; o >>= 1) {
        num += __shfl_down_sync(0xffffffffu, num, o);
        den += __shfl_down_sync(0xffffffffu, den, o);
    }
    __shared__ float sn2[10], sd2[10];
    if (lane == 0) { sn2[warp] = num; sd2[warp] = den; }
    __syncthreads();
    if (t == 0) {
        float fn = 0.0f, fd = 0.0f;
        #pragma unroll
        for (int q = 0; q < 10; q++) { fn += sn2[q]; fd += sd2[q]; }
        out[0] = (fd > 0.0f) ? (fn / fmaxf(fd, EPS_C)) : 0.0f;
    }
}

extern "C" void kernel_launch(void* const* d_in, const int* in_sizes, int n_in,
                              void* d_out, int out_size) {
    (void)n_in; (void)out_size;
    const float* src = (const float*)d_in[0];
    const float* emb = (const float*)d_in[1];
    if (n_in >= 2 && in_sizes[0] == N * D && in_sizes[1] == 2 * N * D) {
        const float* tmp = src; src = emb; emb = tmp;
    }
    float* out = (float*)d_out;

    k_dist<<<NMAT * NTRI32, 256>>>(src, emb);
    k_prep<<<400, 256>>>();
    k_tripart<<<NCH * N, N>>>(out);
}

// round 17
// speedup vs baseline: 1.2685x; 1.0640x over previous
#include <cuda_runtime.h>
#include <math.h>

#define N 320
#define D 128
#define NMAT 3
#define RHO_C 10.0f
#define MARGIN_C 0.2f
#define TAU_C 1.3f
#define SEMIHARD_THRESH_C 0.01f
#define EPS_C 1e-12f
#define NTRI  210                // 20*21/2 lower-triangle 16x16 tiles
#define NCH   4                  // k chunks
#define KCH   80                 // k-chunk size (N/4)
#define PADW 132

typedef unsigned long long ull;

// ---------------- device scratch (no allocations allowed) ----------------
__device__ float  g_d[NMAT][N][N];   // pairwise distances per matrix
__device__ float2 g_mm[NCH][N][N];   // per-chunk (maxs, minn) partials
__device__ float  g_pden[N];         // per-i row sums of pw
__device__ float  g_pnum[N];         // per-i sums of pos*pair_w
__device__ unsigned int g_cnt_i[N];  // per-i chunk tickets
__device__ unsigned int g_counter;   // global ticket for fused final

// ---------------- packed f32x2 helpers (per-lane bit-identical to scalar) ---
__device__ __forceinline__ ull add2(ull a, ull b) {
    ull r; asm("add.rn.f32x2 %0, %1, %2;" : "=l"(r) : "l"(a), "l"(b)); return r;
}
__device__ __forceinline__ ull mul2(ull a, ull b) {
    ull r; asm("mul.rn.f32x2 %0, %1, %2;" : "=l"(r) : "l"(a), "l"(b)); return r;
}
__device__ __forceinline__ ull fma2(ull a, ull b, ull c) {
    ull r; asm("fma.rn.f32x2 %0, %1, %2, %3;" : "=l"(r) : "l"(a), "l"(b), "l"(c)); return r;
}
__device__ __forceinline__ ull pack2(float lo, float hi) {
    ull r; asm("mov.b64 %0, {%1, %2};" : "=l"(r) : "f"(lo), "f"(hi)); return r;
}
__device__ __forceinline__ void unpack2(ull p, float& lo, float& hi) {
    asm("mov.b64 {%0, %1}, %2;" : "=f"(lo), "=f"(hi) : "l"(p));
}

// ---------------- kernel 1: distances; 630 blocks = 210 tiles x 3 mats ------
// (R9/R12 version — best measured total)
__global__ void __launch_bounds__(256) k_dist(const float* __restrict__ src,
                                              const float* __restrict__ emb) {
    int b  = blockIdx.x;
    int m  = b / NTRI;
    int bt = b - m * NTRI;
    int bi = (int)((sqrtf(8.0f * (float)bt + 1.0f) - 1.0f) * 0.5f);
    while ((bi + 1) * (bi + 2) / 2 <= bt) bi++;
    while (bi * (bi + 1) / 2 > bt) bi--;
    int bj = bt - bi * (bi + 1) / 2;
    int i0 = bi * 16, j0 = bj * 16;

    __shared__ float Ai[16][PADW];
    __shared__ float Aj[16][PADW];
    __shared__ float s_sq[32];
    __shared__ float s_ri[32];

    int t  = threadIdx.x;
    int tx = t & 15, ty = t >> 4;
    int lane = t & 31, warp = t >> 5;
    int i = i0 + ty, j = j0 + tx;

    if (b == 0) {                       // reset tickets (precedes k_tripart)
        if (t == 0) g_counter = 0;
        for (int e = t; e < N; e += 256) g_cnt_i[e] = 0;
    }

    const float* base = (m < 2) ? (src + (size_t)m * N * D) : emb;
    for (int e = t; e < 16 * 32; e += 256) {
        int r = e >> 5, c4 = e & 31;
        *(float4*)&Ai[r][c4 * 4] = ((const float4*)(base + (size_t)(i0 + r) * D))[c4];
        *(float4*)&Aj[r][c4 * 4] = ((const float4*)(base + (size_t)(j0 + r) * D))[c4];
    }
    __syncthreads();

    #pragma unroll
    for (int rr = 0; rr < 4; rr++) {
        int row = warp * 4 + rr;
        const float* rp = (row < 16) ? &Ai[row][0] : &Aj[row - 16][0];
        float4 x = ((const float4*)rp)[lane];
        float ssum = x.x * x.x + x.y * x.y + x.z * x.z + x.w * x.w;
        #pragma unroll
        for (int o = 16; o > 0; o >>= 1) ssum += __shfl_xor_sync(0xffffffffu, ssum, o);
        if (lane == 0) {
            float rn = 1.0f / fmaxf(sqrtf(ssum), EPS_C);
            s_sq[row] = ssum * (rn * rn);
            s_ri[row] = rn;
        }
    }
    __syncthreads();

    const float4* ai = (const float4*)&Ai[ty][0];
    const float4* aj = (const float4*)&Aj[tx][0];
    float d0 = 0.f, d1 = 0.f, d2a = 0.f, d3 = 0.f;
    #pragma unroll 8
    for (int c = 0; c < 32; c++) {
        float4 a = ai[c];
        float4 bb = aj[c];
        d0  += a.x * bb.x;
        d1  += a.y * bb.y;
        d2a += a.z * bb.z;
        d3  += a.w * bb.w;
    }
    float dot = (d0 + d1) + (d2a + d3);
    float rij = s_ri[ty] * s_ri[16 + tx];
    float dd  = s_sq[ty] + s_sq[16 + tx] - 2.0f * (dot * rij);
    float d   = sqrtf(fmaxf(dd, 0.0f) + EPS_C);
    g_d[m][i][j] = d;
    if (bi != bj) g_d[m][j][i] = d;    // bitwise symmetric by construction
}

// ---------------- kernel 2: 4-way split-k triplet (f32x2) + final -----------
// grid: 1280 blocks (i = bx>>2, kc = bx&3), 320 threads (one per j).
// Inline pw prologue (no prep kernel); R12's f32x2 2-stream main loop.
__global__ void __launch_bounds__(N) k_tripart(float* __restrict__ out) {
    int i  = blockIdx.x >> 2;
    int kc = blockIdx.x & 3;
    int t  = threadIdx.x;          // j

    __shared__ __align__(16) float sndk[KCH];   // -d_emb[i][k]
    __shared__ __align__(16) float sbk[KCH];    // 1 - pw[i][k]

    // prologue: own-column pw for every thread; chunk records for t < KCH
    float d0j = g_d[0][i][t];
    float d1j = g_d[1][i][t];
    float dij = g_d[2][i][t];
    float pwij = 1.0f / (1.0f + expf(-RHO_C * (TAU_C - 0.5f * (d0j + d1j))));
    if (t < KCH) {
        int c = kc * KCH + t;
        float a0 = g_d[0][i][c];
        float a1 = g_d[1][i][c];
        float de = g_d[2][i][c];
        float pwc = 1.0f / (1.0f + expf(-RHO_C * (TAU_C - 0.5f * (a0 + a1))));
        sndk[t] = -de;
        sbk[t]  = 1.0f - pwc;
    }
    __syncthreads();

    ull dij2  = pack2(dij, dij);
    ull M2    = pack2(MARGIN_C, MARGIN_C);
    float nrpw = -(RHO_C * pwij);
    ull nrpw2 = pack2(nrpw, nrpw);

    float mx0 = 0.0f, mx1 = 0.0f, mx2 = 0.0f, mx3 = 0.0f;
    float mn0 = 1e30f, mn1 = 1e30f, mn2 = 1e30f, mn3 = 1e30f;

    const ulonglong2* pnd = (const ulonglong2*)sndk;
    const ulonglong2* pbk = (const ulonglong2*)sbk;

    // Per lane: tt = dij + (-dk) == -(dk - dij) bitwise; m = M + tt == M - diff.
    // k==j -> tt==0 exactly -> m==0.2f exactly -> semihard (m <= MARGIN).
    #pragma unroll 5
    for (int q = 0; q < KCH / 4; q++) {
        ulonglong2 nd = pnd[q];        // 4 k's of -dk
        ulonglong2 bb = pbk[q];        // 4 k's of bk
        {
            ull t2  = add2(dij2, nd.x);
            ull m2  = add2(M2, t2);
            ull vs2 = mul2(m2, bb.x);
            ull vh2 = fma2(bb.x, nrpw2, m2);
            float m0, m1, vs0, vs1, vh0, vh1;
            unpack2(m2, m0, m1); unpack2(vs2, vs0, vs1); unpack2(vh2, vh0, vh1);
            if (m0 <= MARGIN_C) mx0 = fmaxf(mx0, vs0); else mn0 = fminf(mn0, vh0);
            if (m1 <= MARGIN_C) mx1 = fmaxf(mx1, vs1); else mn1 = fminf(mn1, vh1);
        }
        {
            ull t2  = add2(dij2, nd.y);
            ull m2  = add2(M2, t2);
            ull vs2 = mul2(m2, bb.y);
            ull vh2 = fma2(bb.y, nrpw2, m2);
            float m0, m1, vs0, vs1, vh0, vh1;
            unpack2(m2, m0, m1); unpack2(vs2, vs0, vs1); unpack2(vh2, vh0, vh1);
            if (m0 <= MARGIN_C) mx2 = fmaxf(mx2, vs0); else mn2 = fminf(mn2, vh0);
            if (m1 <= MARGIN_C) mx3 = fmaxf(mx3, vs1); else mn3 = fminf(mn3, vh1);
        }
    }
    float maxs = fmaxf(fmaxf(mx0, mx1), fmaxf(mx2, mx3));  // assoc+comm: bit-exact
    float minn = fminf(fminf(mn0, mn1), fminf(mn2, mn3));

    __stcg(&g_mm[kc][i][t], make_float2(maxs, minn));
    __threadfence();

    // per-i ticket: 4th chunk block to finish combines row i
    __shared__ bool win_i;
    if (t == 0) win_i = (atomicAdd(&g_cnt_i[i], 1u) == (unsigned)(NCH - 1));
    __syncthreads();
    if (!win_i) return;

    float2 c0 = __ldcg(&g_mm[0][i][t]);
    float2 c1 = __ldcg(&g_mm[1][i][t]);
    float2 c2 = __ldcg(&g_mm[2][i][t]);
    float2 c3 = __ldcg(&g_mm[3][i][t]);
    float mx = fmaxf(fmaxf(c0.x, c1.x), fmaxf(c2.x, c3.x));
    float mn = fminf(fminf(c0.y, c1.y), fminf(c2.y, c3.y));
    float psh = pwij * mx;                          // pos_semihard
    float ph  = (mn < 0.0f) ? (mn + RHO_C) : 0.0f;
    float pos = psh + ((psh <= SEMIHARD_THRESH_C) ? ph : 0.0f);
    float contrib = pos * pwij;

    // deterministic dual block reduction: contrib (num) and pwij (den)
    float v = contrib, w = pwij;
    #pragma unroll
    for (int o = 16; o > 0; o >>= 1) {
        v += __shfl_down_sync(0xffffffffu, v, o);
        w += __shfl_down_sync(0xffffffffu, w, o);
    }
    __shared__ float swn[10], swd[10];
    int lane = t & 31, warp = t >> 5;
    if (lane == 0) { swn[warp] = v; swd[warp] = w; }
    __syncthreads();
    if (warp == 0 && lane == 0) {
        float sn = 0.0f, sdv = 0.0f;
        #pragma unroll
        for (int q = 0; q < 10; q++) { sn += swn[q]; sdv += swd[q]; }
        g_pnum[i] = sn;
        g_pden[i] = sdv;
    }

    // ---- fused final: last winning block sums everything ----
    __threadfence();
    __shared__ bool is_last;
    if (t == 0) is_last = (atomicAdd(&g_counter, 1u) == (unsigned)(N - 1));
    __syncthreads();
    if (!is_last) return;

    float num = __ldcg(&g_pnum[t]);
    float den = __ldcg(&g_pden[t]);
    #pragma unroll
    for (int o = 16; o > 0; o >>= 1) {
        num += __shfl_down_sync(0xffffffffu, num, o);
        den += __shfl_down_sync(0xffffffffu, den, o);
    }
    __shared__ float sn2[10], sd2[10];
    if (lane == 0) { sn2[warp] = num; sd2[warp] = den; }
    __syncthreads();
    if (t == 0) {
        float fn = 0.0f, fd = 0.0f;
        #pragma unroll
        for (int q = 0; q < 10; q++) { fn += sn2[q]; fd += sd2[q]; }
        out[0] = (fd > 0.0f) ? (fn / fmaxf(fd, EPS_C)) : 0.0f;
    }
}

extern "C" void kernel_launch(void* const* d_in, const int* in_sizes, int n_in,
                              void* d_out, int out_size) {
    (void)n_in; (void)out_size;
    const float* src = (const float*)d_in[0];
    const float* emb = (const float*)d_in[1];
    if (n_in >= 2 && in_sizes[0] == N * D && in_sizes[1] == 2 * N * D) {
        const float* tmp = src; src = emb; emb = tmp;
    }
    float* out = (float*)d_out;

    k_dist<<<NMAT * NTRI, 256>>>(src, emb);
    k_tripart<<<NCH * N, N>>>(out);
}